// round 2
// baseline (speedup 1.0000x reference)
#include <cuda_runtime.h>

#define BB  2
#define NNq 512
#define DDm 128
#define HHm 8
#define DKK 16

// -------- scratch (static device globals; no allocation) --------
__device__ float g_Q[BB*HHm*NNq*DKK];     // [b][h][n][dk], pre-scaled by DK^-0.5
__device__ float g_K[BB*HHm*NNq*DKK];
__device__ float g_V[BB*HHm*NNq*DKK];
__device__ float g_S[BB*HHm*NNq*NNq];     // clipped scaled scores
__device__ float g_A[BB*HHm*NNq*NNq];     // softmax * dyn_cent
__device__ float g_Vt[BB*NNq*DDm];        // [b][n][h*16+dk]

// ================= K1: QKV projection =================
// grid 128 blocks x 384 threads; each block handles 8 rows of n ([B*N,128] @ [128,384])
__global__ void k_qkv(const float* __restrict__ n_in, const float* __restrict__ W_qkv)
{
    __shared__ __align__(16) float sn[8*128];
    int tid = threadIdx.x;                 // 0..383
    int rowbase = blockIdx.x * 8;
    for (int idx = tid; idx < 8*128; idx += 384)
        sn[idx] = n_in[rowbase*128 + idx];
    __syncthreads();

    int j = tid;                           // output column 0..383
    float acc[8];
#pragma unroll
    for (int r = 0; r < 8; r++) acc[r] = 0.f;
    for (int k = 0; k < 128; k++) {
        float w = W_qkv[k*384 + j];
#pragma unroll
        for (int r = 0; r < 8; r++) acc[r] += sn[r*128 + k] * w;
    }
    int three = j >> 7;
    int h  = (j >> 4) & 7;
    int dk = j & 15;
    float* dst = (three == 0) ? g_Q : (three == 1 ? g_K : g_V);
    float sc = (three == 0) ? 0.25f : 1.0f;   // DK^-0.5 = 1/4 folded into Q
#pragma unroll
    for (int r = 0; r < 8; r++) {
        int row = rowbase + r;
        int b = row >> 9, nn = row & 511;
        dst[((b*HHm + h)*NNq + nn)*DKK + dk] = acc[r] * sc;
    }
}

// ================= K2: scores S = clip(Q K^T) =================
// grid (8 n-tiles, H, B) x 256 threads
__global__ void k_scores()
{
    __shared__ __align__(16) float ksm[NNq*DKK];   // 32 KB
    __shared__ __align__(16) float qsm[64*DKK];    // 4 KB
    int tid = threadIdx.x;
    int nt = blockIdx.x, h = blockIdx.y, b = blockIdx.z;
    int bh = b*HHm + h;
    const float* Kg = g_K + (size_t)bh*NNq*DKK;
    const float* Qg = g_Q + (size_t)bh*NNq*DKK + nt*64*DKK;
    for (int idx = tid; idx < NNq*DKK; idx += 256) ksm[idx] = Kg[idx];
    for (int idx = tid; idx < 64*DKK;  idx += 256) qsm[idx] = Qg[idx];
    __syncthreads();

    int m0 = tid, m1 = tid + 256;
    float kr0[16], kr1[16];
#pragma unroll
    for (int q = 0; q < 4; q++) {
        float4 v = ((const float4*)ksm)[m0*4 + q];
        kr0[q*4+0]=v.x; kr0[q*4+1]=v.y; kr0[q*4+2]=v.z; kr0[q*4+3]=v.w;
        float4 u = ((const float4*)ksm)[m1*4 + q];
        kr1[q*4+0]=u.x; kr1[q*4+1]=u.y; kr1[q*4+2]=u.z; kr1[q*4+3]=u.w;
    }
    float* Srow = g_S + ((size_t)bh*NNq + nt*64)*NNq;
    for (int nl = 0; nl < 64; nl++) {
        float s0 = 0.f, s1 = 0.f;
#pragma unroll
        for (int k = 0; k < 16; k++) {
            float q = qsm[nl*16 + k];
            s0 += q * kr0[k];
            s1 += q * kr1[k];
        }
        s0 = fminf(5.f, fmaxf(-5.f, s0));
        s1 = fminf(5.f, fmaxf(-5.f, s1));
        Srow[(size_t)nl*NNq + m0] = s0;
        Srow[(size_t)nl*NNq + m1] = s1;
    }
}

// ================= K3: fused E/G projection + softmax + e_out =================
// grid B*N = 1024 blocks x 256 threads. Dynamic smem layout (floats):
//   sEc : 512*36  = 18432   e chunk [512 rows][32 k], pad 36 (conflict-free, 16B aligned)
//   sEm : 8*512   = 4096    _E matrix [h][m]
//   sW  : 128*16  = 2048    [k][h]: h<8 -> W_e, h>=8 -> W_g
//   sGs : 32                per-head G sums
#define K3_SEC  18432
#define K3_SEM  4096
#define K3_SW   2048
#define K3_SMEM ((K3_SEC + K3_SEM + K3_SW + 32) * 4)

__global__ void __launch_bounds__(256) k_fused(
    const float* __restrict__ e_in,
    const float* __restrict__ W_g, const float* __restrict__ W_e,
    const float* __restrict__ O_e, float* __restrict__ e_out)
{
    extern __shared__ __align__(16) float sm[];
    float* sEc = sm;
    float* sEm = sm + K3_SEC;
    float* sW  = sm + K3_SEC + K3_SEM;
    float* sGs = sm + K3_SEC + K3_SEM + K3_SW;

    int tid = threadIdx.x;
    int bn = blockIdx.x;
    int b = bn >> 9, n = bn & 511;

    for (int idx = tid; idx < 2048; idx += 256) {
        int k = idx >> 4, h = idx & 15;
        sW[idx] = (h < 8) ? W_e[k*8 + h] : W_g[k*8 + (h - 8)];
    }
    if (tid < 8) sGs[tid] = 0.f;
    __syncthreads();

    const float* e_base = e_in + (size_t)bn * NNq * DDm;
    int h4 = tid & 3;        // output col group
    int rg = tid >> 2;       // 0..63 ; rows rg + 64*i

    float acc[8][4];
#pragma unroll
    for (int i = 0; i < 8; i++)
#pragma unroll
        for (int j = 0; j < 4; j++) acc[i][j] = 0.f;

    for (int kc = 0; kc < 128; kc += 32) {
        // stage e[:, kc:kc+32] -> sEc (float4, coalesced)
#pragma unroll
        for (int i = 0; i < 16; i++) {
            int lin4 = tid + 256*i;            // 0..4095
            int r = lin4 >> 3, c4 = lin4 & 7;
            float4 v = *(const float4*)(e_base + (size_t)r*DDm + kc + c4*4);
            *(float4*)(sEc + r*36 + c4*4) = v;
        }
        __syncthreads();
#pragma unroll
        for (int k = 0; k < 32; k++) {
            float w0 = sW[(kc+k)*16 + h4];
            float w1 = sW[(kc+k)*16 + h4 + 4];
            float w2 = sW[(kc+k)*16 + h4 + 8];
            float w3 = sW[(kc+k)*16 + h4 + 12];
#pragma unroll
            for (int i = 0; i < 8; i++) {
                float ev = sEc[(rg + 64*i)*36 + k];
                acc[i][0] += ev * w0;
                acc[i][1] += ev * w1;
                acc[i][2] += ev * w2;
                acc[i][3] += ev * w3;
            }
        }
        __syncthreads();
    }

    // cols: h4 -> E head h4 ; h4+4 -> E head h4+4 ; h4+8 -> G head h4 ; h4+12 -> G head h4+4
#pragma unroll
    for (int i = 0; i < 8; i++) {
        int r = rg + 64*i;
        sEm[h4*512 + r]       = acc[i][0];
        sEm[(h4+4)*512 + r]   = acc[i][1];
    }
    float gs0 = 0.f, gs1 = 0.f;
#pragma unroll
    for (int i = 0; i < 8; i++) {
        gs0 += 1.f / (1.f + expf(-acc[i][2]));
        gs1 += 1.f / (1.f + expf(-acc[i][3]));
    }
    atomicAdd(&sGs[h4],     gs0);
    atomicAdd(&sGs[h4 + 4], gs1);
    __syncthreads();

    // _E = S + E  (coalesced S rows)
    for (int idx = tid; idx < 4096; idx += 256) {
        int h = idx >> 9, m = idx & 511;
        sEm[idx] += g_S[(((size_t)b*HHm + h)*NNq + n)*NNq + m];
    }
    __syncthreads();

    // softmax per head (warp w -> head w), fold dyn_cent; write A scratch
    {
        int warp = tid >> 5, lane = tid & 31;
        int h = warp;
        const float* row = sEm + h*512;
        float mx = -1e30f;
#pragma unroll
        for (int j = 0; j < 16; j++) mx = fmaxf(mx, row[lane + 32*j]);
#pragma unroll
        for (int o = 16; o > 0; o >>= 1) mx = fmaxf(mx, __shfl_xor_sync(0xffffffffu, mx, o));
        float s = 0.f;
#pragma unroll
        for (int j = 0; j < 16; j++) s += expf(row[lane + 32*j] - mx);
#pragma unroll
        for (int o = 16; o > 0; o >>= 1) s += __shfl_xor_sync(0xffffffffu, s, o);
        float dc  = log1pf(sGs[h]);
        float inv = dc / s;
        float* Arow = g_A + (((size_t)b*HHm + h)*NNq + n)*NNq;
#pragma unroll
        for (int j = 0; j < 16; j++) {
            int m = lane + 32*j;
            Arow[m] = expf(row[m] - mx) * inv;
        }
    }

    // e_out[b,n,m,:] = sum_h _E[h][m] * O_e[h][:]   (O_e in registers, fully coalesced)
    {
        int d4 = tid & 31, mg = tid >> 5;
        float oe[8][4];
#pragma unroll
        for (int h = 0; h < 8; h++) {
            float4 v = ((const float4*)O_e)[h*32 + d4];
            oe[h][0] = v.x; oe[h][1] = v.y; oe[h][2] = v.z; oe[h][3] = v.w;
        }
        float* erow_base = e_out + (size_t)bn * NNq * DDm;
        for (int mi = 0; mi < 64; mi++) {
            int m = mg + 8*mi;
            float E8[8];
#pragma unroll
            for (int h = 0; h < 8; h++) E8[h] = sEm[h*512 + m];
            float4 o; o.x = o.y = o.z = o.w = 0.f;
#pragma unroll
            for (int h = 0; h < 8; h++) {
                o.x += E8[h]*oe[h][0];
                o.y += E8[h]*oe[h][1];
                o.z += E8[h]*oe[h][2];
                o.w += E8[h]*oe[h][3];
            }
            *(float4*)(erow_base + (size_t)m*DDm + d4*4) = o;
        }
    }
}

// ================= K4: _V = (A * dc) @ V =================
// grid (8 n-tiles, H, B) x 256 threads
__global__ void k_av()
{
    __shared__ __align__(16) float As[64*129];   // ~33 KB
    __shared__ __align__(16) float Vsc[128*16];  // 8 KB
    int tid = threadIdx.x;
    int nt = blockIdx.x, h = blockIdx.y, b = blockIdx.z;
    int bh = b*HHm + h;
    int nbase = nt*64;
    int dk8 = tid & 7;
    int ng  = tid >> 3;     // 0..31 ; rows ng, ng+32

    float a00 = 0.f, a01 = 0.f, a10 = 0.f, a11 = 0.f;
    for (int mc = 0; mc < 512; mc += 128) {
        for (int idx = tid; idx < 64*128; idx += 256) {
            int r = idx >> 7, c = idx & 127;
            As[r*129 + c] = g_A[((size_t)bh*NNq + nbase + r)*NNq + mc + c];
        }
        for (int idx = tid; idx < 128*16; idx += 256)
            Vsc[idx] = g_V[((size_t)bh*NNq + mc)*DKK + idx];
        __syncthreads();
#pragma unroll 8
        for (int m = 0; m < 128; m++) {
            float v0 = Vsc[m*16 + dk8];
            float v1 = Vsc[m*16 + dk8 + 8];
            float x0 = As[ng*129 + m];
            float x1 = As[(ng+32)*129 + m];
            a00 += x0*v0; a01 += x0*v1;
            a10 += x1*v0; a11 += x1*v1;
        }
        __syncthreads();
    }
    size_t r0 = ((size_t)b*NNq + nbase + ng)*DDm + h*16;
    size_t r1 = ((size_t)b*NNq + nbase + ng + 32)*DDm + h*16;
    g_Vt[r0 + dk8]     = a00;
    g_Vt[r0 + dk8 + 8] = a01;
    g_Vt[r1 + dk8]     = a10;
    g_Vt[r1 + dk8 + 8] = a11;
}

// ================= K5: n_out = _V @ O_n =================
__global__ void k_nout(const float* __restrict__ O_n, float* __restrict__ out)
{
    __shared__ __align__(16) float sv[128];
    int row = blockIdx.x;
    int tid = threadIdx.x;   // 128
    sv[tid] = g_Vt[(size_t)row*128 + tid];
    __syncthreads();
    float acc = 0.f;
#pragma unroll 8
    for (int k = 0; k < 128; k++) acc += sv[k] * O_n[k*128 + tid];
    out[(size_t)row*128 + tid] = acc;
}

// ================= launch =================
extern "C" void kernel_launch(void* const* d_in, const int* in_sizes, int n_in,
                              void* d_out, int out_size)
{
    const float* n_in_p = (const float*)d_in[0];
    const float* e_in   = (const float*)d_in[1];
    const float* W_qkv  = (const float*)d_in[2];
    const float* O_n    = (const float*)d_in[3];
    const float* W_g    = (const float*)d_in[4];
    const float* W_e    = (const float*)d_in[5];
    const float* O_e    = (const float*)d_in[6];

    float* out   = (float*)d_out;
    float* n_out = out;                       // [B,N,D] first
    float* e_out = out + (size_t)BB*NNq*DDm;  // then [B,N,N,D]

    cudaFuncSetAttribute(k_fused, cudaFuncAttributeMaxDynamicSharedMemorySize, K3_SMEM);

    k_qkv   <<<128, 384>>>(n_in_p, W_qkv);
    k_scores<<<dim3(8, HHm, BB), 256>>>();
    k_fused <<<BB*NNq, 256, K3_SMEM>>>(e_in, W_g, W_e, O_e, e_out);
    k_av    <<<dim3(8, HHm, BB), 256>>>();
    k_nout  <<<BB*NNq, 128>>>(O_n, n_out);
}

// round 3
// speedup vs baseline: 1.0574x; 1.0574x over previous
#include <cuda_runtime.h>
#include <cstdint>

#define BB  2
#define NNq 512
#define DDm 128
#define HHm 8
#define DKK 16

// -------- scratch (static device globals; no allocation) --------
__device__ float g_Q[BB*HHm*NNq*DKK];     // pre-scaled by DK^-0.5
__device__ float g_K[BB*HHm*NNq*DKK];
__device__ float g_V[BB*HHm*NNq*DKK];
__device__ float g_S[BB*HHm*NNq*NNq];     // clipped scaled scores

__device__ __forceinline__ void cp16(uint32_t dst, const void* src) {
    asm volatile("cp.async.cg.shared.global [%0], [%1], 16;" :: "r"(dst), "l"(src));
}
__device__ __forceinline__ void cp_commit() {
    asm volatile("cp.async.commit_group;");
}
template<int N>
__device__ __forceinline__ void cp_wait() {
    asm volatile("cp.async.wait_group %0;" :: "n"(N));
}

// ================= K1: QKV projection =================
__global__ void k_qkv(const float* __restrict__ n_in, const float* __restrict__ W_qkv)
{
    __shared__ __align__(16) float sn[8*128];
    int tid = threadIdx.x;                 // 0..383
    int rowbase = blockIdx.x * 8;
    for (int idx = tid; idx < 8*128; idx += 384)
        sn[idx] = n_in[rowbase*128 + idx];
    __syncthreads();

    int j = tid;
    float acc[8];
#pragma unroll
    for (int r = 0; r < 8; r++) acc[r] = 0.f;
    for (int k = 0; k < 128; k++) {
        float w = W_qkv[k*384 + j];
#pragma unroll
        for (int r = 0; r < 8; r++) acc[r] += sn[r*128 + k] * w;
    }
    int three = j >> 7;
    int h  = (j >> 4) & 7;
    int dk = j & 15;
    float* dst = (three == 0) ? g_Q : (three == 1 ? g_K : g_V);
    float sc = (three == 0) ? 0.25f : 1.0f;
#pragma unroll
    for (int r = 0; r < 8; r++) {
        int row = rowbase + r;
        int b = row >> 9, nn = row & 511;
        dst[((b*HHm + h)*NNq + nn)*DKK + dk] = acc[r] * sc;
    }
}

// ================= K2: scores S = clip(Q K^T) =================
__global__ void k_scores()
{
    __shared__ __align__(16) float ksm[NNq*DKK];
    __shared__ __align__(16) float qsm[64*DKK];
    int tid = threadIdx.x;
    int nt = blockIdx.x, h = blockIdx.y, b = blockIdx.z;
    int bh = b*HHm + h;
    const float* Kg = g_K + (size_t)bh*NNq*DKK;
    const float* Qg = g_Q + (size_t)bh*NNq*DKK + nt*64*DKK;
    for (int idx = tid; idx < NNq*DKK; idx += 256) ksm[idx] = Kg[idx];
    for (int idx = tid; idx < 64*DKK;  idx += 256) qsm[idx] = Qg[idx];
    __syncthreads();

    int m0 = tid, m1 = tid + 256;
    float kr0[16], kr1[16];
#pragma unroll
    for (int q = 0; q < 4; q++) {
        float4 v = ((const float4*)ksm)[m0*4 + q];
        kr0[q*4+0]=v.x; kr0[q*4+1]=v.y; kr0[q*4+2]=v.z; kr0[q*4+3]=v.w;
        float4 u = ((const float4*)ksm)[m1*4 + q];
        kr1[q*4+0]=u.x; kr1[q*4+1]=u.y; kr1[q*4+2]=u.z; kr1[q*4+3]=u.w;
    }
    float* Srow = g_S + ((size_t)bh*NNq + nt*64)*NNq;
    for (int nl = 0; nl < 64; nl++) {
        float s0 = 0.f, s1 = 0.f;
#pragma unroll
        for (int k = 0; k < 16; k++) {
            float q = qsm[nl*16 + k];
            s0 += q * kr0[k];
            s1 += q * kr1[k];
        }
        s0 = fminf(5.f, fmaxf(-5.f, s0));
        s1 = fminf(5.f, fmaxf(-5.f, s1));
        Srow[(size_t)nl*NNq + m0] = s0;
        Srow[(size_t)nl*NNq + m1] = s1;
    }
}

// ================= K3: mega-fused =================
// E/G projection (cp.async double-buffered) + S add + e_out + softmax + AV + n_out
// smem (floats):
//   sEc : 2 stages * 512*20 = 20480  (e chunk [512 rows][16 k], pad 20)
//   sEm : 8*512  = 4096              _E matrix [h][m], later A in place
//   sW  : 128*16 = 2048              [k][h]: h<8 W_e, h>=8 W_g
//   sGs : 32
//   sVt : 128                        _V row [h*16+dk]
#define CHUNK    16
#define PADW     20
#define SEC1     (NNq*PADW)          // 10240
#define OFF_SEM  (2*SEC1)            // 20480
#define OFF_SW   (OFF_SEM + 4096)    // 24576
#define OFF_GS   (OFF_SW + 2048)     // 26624
#define OFF_VT   (OFF_GS + 32)       // 26656
#define K3_FLOATS (OFF_VT + 160)     // pad
#define K3_SMEM  (K3_FLOATS * 4)

__global__ void __launch_bounds__(256) k_fused(
    const float* __restrict__ e_in,
    const float* __restrict__ W_g, const float* __restrict__ W_e,
    const float* __restrict__ O_e, const float* __restrict__ O_n,
    float* __restrict__ e_out, float* __restrict__ n_out)
{
    extern __shared__ __align__(16) float sm[];
    float* sEm = sm + OFF_SEM;
    float* sW  = sm + OFF_SW;
    float* sGs = sm + OFF_GS;
    float* sVt = sm + OFF_VT;
    uint32_t sbase = (uint32_t)__cvta_generic_to_shared(sm);

    int tid = threadIdx.x;
    int bn = blockIdx.x;
    int b = bn >> 9, n = bn & 511;
    const float* e_base = e_in + (size_t)bn * NNq * DDm;

    // ---- issue chunk 0 immediately ----
    {
#pragma unroll
        for (int i = 0; i < 8; i++) {
            int idx = tid + 256*i;           // 0..2047 float4 slots
            int r = idx >> 2, c4 = idx & 3;
            cp16(sbase + (uint32_t)(0*SEC1 + r*PADW + c4*4)*4u,
                 e_base + (size_t)r*DDm + 0 + c4*4);
        }
        cp_commit();
    }

    // ---- weights into smem (overlaps with chunk0 in flight) ----
    for (int idx = tid; idx < 2048; idx += 256) {
        int k = idx >> 4, h = idx & 15;
        sW[idx] = (h < 8) ? W_e[k*8 + h] : W_g[k*8 + (h - 8)];
    }
    if (tid < 8) sGs[tid] = 0.f;

    int h4 = tid & 3;
    int rg = tid >> 2;    // 0..63

    float acc[8][4];
#pragma unroll
    for (int i = 0; i < 8; i++)
#pragma unroll
        for (int j = 0; j < 4; j++) acc[i][j] = 0.f;

    // ---- pipelined GEMM over 8 chunks of k=16 ----
    for (int c = 0; c < 8; c++) {
        if (c < 7) {
            int kc = (c+1)*CHUNK;
            int s  = (c+1) & 1;
#pragma unroll
            for (int i = 0; i < 8; i++) {
                int idx = tid + 256*i;
                int r = idx >> 2, c4 = idx & 3;
                cp16(sbase + (uint32_t)(s*SEC1 + r*PADW + c4*4)*4u,
                     e_base + (size_t)r*DDm + kc + c4*4);
            }
            cp_commit();
            cp_wait<1>();
        } else {
            cp_wait<0>();
        }
        __syncthreads();

        const float* sEc = sm + (c & 1)*SEC1;
        int kc = c*CHUNK;
#pragma unroll
        for (int k = 0; k < CHUNK; k++) {
            float w0 = sW[(kc+k)*16 + h4];
            float w1 = sW[(kc+k)*16 + h4 + 4];
            float w2 = sW[(kc+k)*16 + h4 + 8];
            float w3 = sW[(kc+k)*16 + h4 + 12];
#pragma unroll
            for (int i = 0; i < 8; i++) {
                float ev = sEc[(rg + 64*i)*PADW + k];
                acc[i][0] += ev * w0;
                acc[i][1] += ev * w1;
                acc[i][2] += ev * w2;
                acc[i][3] += ev * w3;
            }
        }
        __syncthreads();
    }

    // ---- prefetch O_n into freed staging area (consumed at the very end) ----
#pragma unroll
    for (int i = 0; i < 16; i++) {
        int idx = tid + 256*i;               // 0..4095 float4 = 16384 floats
        cp16(sbase + (uint32_t)idx*16u, O_n + idx*4);
    }
    cp_commit();

    // ---- deposit E, sigmoid-sum G ----
#pragma unroll
    for (int i = 0; i < 8; i++) {
        int r = rg + 64*i;
        sEm[h4*512 + r]     = acc[i][0];
        sEm[(h4+4)*512 + r] = acc[i][1];
    }
    float gs0 = 0.f, gs1 = 0.f;
#pragma unroll
    for (int i = 0; i < 8; i++) {
        gs0 += 1.f / (1.f + expf(-acc[i][2]));
        gs1 += 1.f / (1.f + expf(-acc[i][3]));
    }
    atomicAdd(&sGs[h4],     gs0);
    atomicAdd(&sGs[h4 + 4], gs1);
    __syncthreads();

    // ---- _E = S + E ----
    for (int idx = tid; idx < 4096; idx += 256) {
        int h = idx >> 9, m = idx & 511;
        sEm[idx] += g_S[(((size_t)b*HHm + h)*NNq + n)*NNq + m];
    }
    __syncthreads();

    // ---- e_out = _E^T @ O_e  (O_e in registers, coalesced float4 stores) ----
    {
        int d4 = tid & 31, mg = tid >> 5;
        float oe[8][4];
#pragma unroll
        for (int h = 0; h < 8; h++) {
            float4 v = ((const float4*)O_e)[h*32 + d4];
            oe[h][0] = v.x; oe[h][1] = v.y; oe[h][2] = v.z; oe[h][3] = v.w;
        }
        float* erow_base = e_out + (size_t)bn * NNq * DDm;
        for (int mi = 0; mi < 64; mi++) {
            int m = mg + 8*mi;
            float E8[8];
#pragma unroll
            for (int h = 0; h < 8; h++) E8[h] = sEm[h*512 + m];
            float4 o; o.x = o.y = o.z = o.w = 0.f;
#pragma unroll
            for (int h = 0; h < 8; h++) {
                o.x += E8[h]*oe[h][0];
                o.y += E8[h]*oe[h][1];
                o.z += E8[h]*oe[h][2];
                o.w += E8[h]*oe[h][3];
            }
            *(float4*)(erow_base + (size_t)m*DDm + d4*4) = o;
        }
    }
    __syncthreads();   // everyone done reading _E before in-place softmax

    // ---- softmax per head (warp h), in place, dyn_cent folded; then AV ----
    {
        int h = tid >> 5, lane = tid & 31;
        float* row = sEm + h*512;
        float mx = -1e30f;
#pragma unroll
        for (int j = 0; j < 16; j++) mx = fmaxf(mx, row[lane + 32*j]);
#pragma unroll
        for (int o = 16; o > 0; o >>= 1) mx = fmaxf(mx, __shfl_xor_sync(0xffffffffu, mx, o));
        float s = 0.f;
        float p[16];
#pragma unroll
        for (int j = 0; j < 16; j++) { p[j] = expf(row[lane + 32*j] - mx); s += p[j]; }
#pragma unroll
        for (int o = 16; o > 0; o >>= 1) s += __shfl_xor_sync(0xffffffffu, s, o);
        float inv = log1pf(sGs[h]) / s;
#pragma unroll
        for (int j = 0; j < 16; j++) row[lane + 32*j] = p[j] * inv;
        __syncwarp();

        // AV: warp h computes _V[h][0..15]; lanes: dk = lane&15, mh = lane>>4
        int dk = lane & 15, mh = lane >> 4;
        const float* Vg = g_V + ((size_t)(b*HHm + h)*NNq)*DKK;
        float a0 = 0.f, a1 = 0.f, a2 = 0.f, a3 = 0.f;
#pragma unroll 4
        for (int it = 0; it < 256; it += 4) {
            int m0 = 2*it + mh;
            a0 += row[m0]     * Vg[(size_t)m0*16     + dk];
            a1 += row[m0 + 2] * Vg[(size_t)(m0+2)*16 + dk];
            a2 += row[m0 + 4] * Vg[(size_t)(m0+4)*16 + dk];
            a3 += row[m0 + 6] * Vg[(size_t)(m0+6)*16 + dk];
        }
        float v = (a0 + a1) + (a2 + a3);
        v += __shfl_xor_sync(0xffffffffu, v, 16);
        if (lane < 16) sVt[h*16 + dk] = v;
    }
    __syncthreads();

    // ---- n_out = _V @ O_n (O_n prefetched into sm[0..16384)) ----
    cp_wait<0>();
    __syncthreads();
    if (tid < 128) {
        float a0 = 0.f, a1 = 0.f;
#pragma unroll 4
        for (int k = 0; k < 128; k += 2) {
            a0 += sVt[k]   * sm[k*128 + tid];
            a1 += sVt[k+1] * sm[(k+1)*128 + tid];
        }
        n_out[(size_t)bn*128 + tid] = a0 + a1;
    }
}

// ================= launch =================
extern "C" void kernel_launch(void* const* d_in, const int* in_sizes, int n_in,
                              void* d_out, int out_size)
{
    const float* n_in_p = (const float*)d_in[0];
    const float* e_in   = (const float*)d_in[1];
    const float* W_qkv  = (const float*)d_in[2];
    const float* O_n    = (const float*)d_in[3];
    const float* W_g    = (const float*)d_in[4];
    const float* W_e    = (const float*)d_in[5];
    const float* O_e    = (const float*)d_in[6];

    float* out   = (float*)d_out;
    float* n_out = out;
    float* e_out = out + (size_t)BB*NNq*DDm;

    cudaFuncSetAttribute(k_fused, cudaFuncAttributeMaxDynamicSharedMemorySize, K3_SMEM);

    k_qkv   <<<128, 384>>>(n_in_p, W_qkv);
    k_scores<<<dim3(8, HHm, BB), 256>>>();
    k_fused <<<BB*NNq, 256, K3_SMEM>>>(e_in, W_g, W_e, O_e, O_n, e_out, n_out);
}